// round 15
// baseline (speedup 1.0000x reference)
#include <cuda_runtime.h>
#include <cuda_bf16.h>
#include <cuda_fp16.h>
#include <math.h>
#include <cstdint>

// ---------------------------------------------------------------------------
// LSAMCell — Round 15.
//   Overlap GEMM compute with am_update DRAM streaming via a heterogeneous
//   mixed launch (single stream, no spin-waits):
//     1) gemm_half  : m-blocks 0-3 (132 CTAs, ~1/SM, solo-rate)
//     2) mix        : gemm m-blocks 4-7 (132 blocks) + am units b<512 (4096)
//     3) am_half    : am units b>=512
//   Base kernels from R14 (k-major W, trans-ldmatrix B, fp16 K=2048 GEMM).
// ---------------------------------------------------------------------------

#define B_      1024
#define NQKV    3072
#define NPADW   3168               // g_W row width (33 tiles of 96)
#define KW      2048
#define NHEAD_  16
#define DHEAD   64

#define TM      128
#define TN      96
#define BK      64
#define STAGES  3
#define NST     32                 // 2048 / 64
#define PITCH   144                // A tile pitch
#define PITCHB  208                // B tile pitch (192B data + 16B skew)
#define TILE_A  (TM * PITCH)       // 18432
#define TILE_Bz (BK * PITCHB)      // 13312
#define STAGE_BYTES (TILE_A + TILE_Bz)       // 31744
#define SMEM_TOTAL  (STAGES * STAGE_BYTES)   // 95232

#define GEMM_MIX_CTAS 132          // 33 n-tiles x 4 m-blocks in mix launch

__device__ float g_qkv[B_ * NQKV];
__device__ float g_wr [B_ * 32];
__device__ __align__(16) __half g_A[B_ * KW];      // fp16(xh), m-major
__device__ __align__(16) __half g_W[KW * NPADW];   // fp16(W), K-MAJOR; cols 3104.. zero

// ---------------------------------------------------------------------------
__device__ __forceinline__ uint32_t smem_u32(const void* p) {
    uint32_t a;
    asm("{ .reg .u64 t; cvta.to.shared.u64 t, %1; cvt.u32.u64 %0, t; }" : "=r"(a) : "l"(p));
    return a;
}
__device__ __forceinline__ void cp16(uint32_t dst, const void* src) {
    asm volatile("cp.async.cg.shared.global [%0], [%1], 16;" :: "r"(dst), "l"(src));
}
#define CP_COMMIT() asm volatile("cp.async.commit_group;" ::: "memory")
#define CP_WAIT(n)  asm volatile("cp.async.wait_group %0;" :: "n"(n) : "memory")

__device__ __forceinline__ void ldsm_x4(uint32_t (&r)[4], uint32_t addr) {
    asm volatile("ldmatrix.sync.aligned.m8n8.x4.shared.b16 {%0,%1,%2,%3}, [%4];"
                 : "=r"(r[0]), "=r"(r[1]), "=r"(r[2]), "=r"(r[3]) : "r"(addr));
}
__device__ __forceinline__ void ldsm_x4_t(uint32_t (&r)[4], uint32_t addr) {
    asm volatile("ldmatrix.sync.aligned.m8n8.x4.trans.shared.b16 {%0,%1,%2,%3}, [%4];"
                 : "=r"(r[0]), "=r"(r[1]), "=r"(r[2]), "=r"(r[3]) : "r"(addr));
}
__device__ __forceinline__ void mma16816(
    float (&c)[4], const uint32_t (&a)[4], uint32_t b0, uint32_t b1) {
    asm volatile(
        "mma.sync.aligned.m16n8k16.row.col.f32.f16.f16.f32 "
        "{%0,%1,%2,%3}, {%4,%5,%6,%7}, {%8,%9}, {%0,%1,%2,%3};"
        : "+f"(c[0]), "+f"(c[1]), "+f"(c[2]), "+f"(c[3])
        : "r"(a[0]), "r"(a[1]), "r"(a[2]), "r"(a[3]), "r"(b0), "r"(b1));
}

// ---------------------------------------------------------------------------
// merged conversion kernel (pure streaming, no smem) — R14
// ---------------------------------------------------------------------------
__global__ __launch_bounds__(256) void conv_all(
    const float* __restrict__ X, const float* __restrict__ H,
    const float* __restrict__ W,
    const float* __restrict__ Ww, const float* __restrict__ Wr)
{
    const int bid = blockIdx.x;
    const int t   = threadIdx.x;

    if (bid < 1024) {
        #pragma unroll
        for (int it = 0; it < 2; it++) {
            int f = bid * 512 + t + it * 256;
            int m = f >> 9;
            int k = (f & 511) * 4;
            const float* src = (k < 1024) ? (X + (size_t)m * 1024 + k)
                                          : (H + (size_t)m * 1024 + (k - 1024));
            float4 v = *reinterpret_cast<const float4*>(src);
            __half hi[4];
            hi[0] = __float2half_rn(v.x);
            hi[1] = __float2half_rn(v.y);
            hi[2] = __float2half_rn(v.z);
            hi[3] = __float2half_rn(v.w);
            *reinterpret_cast<uint2*>(&g_A[(size_t)m * KW + k]) = *reinterpret_cast<uint2*>(hi);
        }
    } else if (bid < 4096) {
        #pragma unroll
        for (int it = 0; it < 2; it++) {
            int f = (bid - 1024) * 512 + t + it * 256;
            int k  = f / 768;
            int n4 = (f - k * 768) * 4;
            float4 v = *reinterpret_cast<const float4*>(&W[(size_t)k * NQKV + n4]);
            __half hi[4];
            hi[0] = __float2half_rn(v.x);
            hi[1] = __float2half_rn(v.y);
            hi[2] = __float2half_rn(v.z);
            hi[3] = __float2half_rn(v.w);
            *reinterpret_cast<uint2*>(&g_W[(size_t)k * NPADW + n4]) =
                *reinterpret_cast<uint2*>(hi);
        }
    } else {
        int idx = (bid - 4096) * 256 + t;
        int k = idx >> 5;
        int c = idx & 31;
        float v = (c < 16) ? Ww[(size_t)k * 16 + c] : Wr[(size_t)k * 16 + (c - 16)];
        g_W[(size_t)k * NPADW + NQKV + c] = __float2half_rn(v);
    }
}

// ---------------------------------------------------------------------------
// GEMM body (R14): CTA 128x96, BK=64, 3-stage cp.async, trans-B.
// ---------------------------------------------------------------------------
__device__ __forceinline__ void load_stage(uint32_t sb, int t, int bm, int bn)
{
    const int tid = threadIdx.x;
    const uint32_t base = sb + (t % STAGES) * STAGE_BYTES;
    const __half* gA = g_A + t * BK;
    const __half* gB = g_W + (size_t)(t * BK) * NPADW + bn;
    #pragma unroll
    for (int i = 0; i < 4; i++) {
        int c = tid + i * 256;
        int row = c >> 3, cc = c & 7;
        cp16(base + row * PITCH + cc * 16, gA + (size_t)(bm + row) * KW + cc * 8);
    }
    #pragma unroll
    for (int i = 0; i < 3; i++) {
        int c = tid + i * 256;
        int row = c / 12, cc = c - row * 12;
        cp16(base + TILE_A + row * PITCHB + cc * 16,
             gB + (size_t)row * NPADW + cc * 8);
    }
    CP_COMMIT();
}

__device__ __forceinline__ void gemm_body(
    uint32_t sb, int bm, int bn,
    const float* __restrict__ bias,
    const float* __restrict__ wb, const float* __restrict__ rb)
{
    const int tid  = threadIdx.x;
    const int lane = tid & 31, wid = tid >> 5;
    const int wm = (wid & 3) * 32;
    const int wn = (wid >> 2) * 48;

    const int grp = lane >> 3;
    const int l7  = lane & 7;
    const int arow = wm + (grp & 1) * 8 + l7;
    const int achk = grp >> 1;
    const int bkrow = (grp & 1) * 8 + l7;
    const int bncol = wn + (grp >> 1) * 8;

    float acc[2][6][4];
    #pragma unroll
    for (int i = 0; i < 2; i++)
        #pragma unroll
        for (int j = 0; j < 6; j++)
            #pragma unroll
            for (int l = 0; l < 4; l++) acc[i][j][l] = 0.0f;

    load_stage(sb, 0, bm, bn);
    load_stage(sb, 1, bm, bn);

    for (int s = 0; s < NST; s++) {
        if (s + 2 < NST) { load_stage(sb, s + 2, bm, bn); CP_WAIT(2); }
        else if (s + 1 < NST) { CP_WAIT(1); }
        else { CP_WAIT(0); }
        __syncthreads();

        const uint32_t abase = sb + (s % STAGES) * STAGE_BYTES;
        const uint32_t bbase = abase + TILE_A;

        #pragma unroll
        for (int ks = 0; ks < 4; ks++) {
            uint32_t a[2][4], b[3][4];
            #pragma unroll
            for (int mf = 0; mf < 2; mf++)
                ldsm_x4(a[mf], abase + (arow + mf * 16) * PITCH + (achk + 2 * ks) * 16);
            #pragma unroll
            for (int nf = 0; nf < 3; nf++)
                ldsm_x4_t(b[nf], bbase + (ks * 16 + bkrow) * PITCHB
                                       + (bncol + nf * 16) * 2);
            #pragma unroll
            for (int mf = 0; mf < 2; mf++)
                #pragma unroll
                for (int nf = 0; nf < 3; nf++) {
                    mma16816(acc[mf][nf * 2 + 0], a[mf], b[nf][0], b[nf][1]);
                    mma16816(acc[mf][nf * 2 + 1], a[mf], b[nf][2], b[nf][3]);
                }
        }
        __syncthreads();
    }

    const int q = lane >> 2;
    const int n2 = (lane & 3) * 2;

    if (bn < NQKV) {
        #pragma unroll
        for (int ng = 0; ng < 6; ng++) {
            const int gn = bn + wn + ng * 8 + n2;
            const float bx = bias[gn], by = bias[gn + 1];
            #pragma unroll
            for (int mf = 0; mf < 2; mf++) {
                const int gm = bm + wm + mf * 16 + q;
                float2 lo = { acc[mf][ng][0] + bx, acc[mf][ng][1] + by };
                float2 hi = { acc[mf][ng][2] + bx, acc[mf][ng][3] + by };
                *reinterpret_cast<float2*>(&g_qkv[(size_t)gm * NQKV + gn])       = lo;
                *reinterpret_cast<float2*>(&g_qkv[(size_t)(gm + 8) * NQKV + gn]) = hi;
            }
        }
    } else {
        if (wn == 0) {
            #pragma unroll
            for (int ng = 0; ng < 4; ng++) {
                const int c0 = ng * 8 + n2;
                const float b0 = (c0 < 16) ? wb[c0] : rb[c0 - 16];
                const float b1 = (c0 + 1 < 16) ? wb[c0 + 1] : rb[c0 + 1 - 16];
                #pragma unroll
                for (int mf = 0; mf < 2; mf++) {
                    const int gm = bm + wm + mf * 16 + q;
                    g_wr[(size_t)gm * 32 + c0]     = 1.0f / (1.0f + expf(-(acc[mf][ng][0] + b0)));
                    g_wr[(size_t)gm * 32 + c0 + 1] = 1.0f / (1.0f + expf(-(acc[mf][ng][1] + b1)));
                    g_wr[(size_t)(gm + 8) * 32 + c0]     = 1.0f / (1.0f + expf(-(acc[mf][ng][2] + b0)));
                    g_wr[(size_t)(gm + 8) * 32 + c0 + 1] = 1.0f / (1.0f + expf(-(acc[mf][ng][3] + b1)));
                }
            }
        }
    }
}

// ---------------------------------------------------------------------------
// am body (R12 measured-best): 2 units per 256-thread block.
// ---------------------------------------------------------------------------
__device__ __forceinline__ void am_body(
    int bh_base, const float* __restrict__ AM,
    float* __restrict__ hout, float* __restrict__ AMout)
{
    __shared__ float qs[2][64], ks2[2][64], vs[2][64];
    __shared__ float dks[2][64], dqs[2][64], vps[2][64];
    __shared__ float scq[2], sck[2], kqd[2];

    const int tid = threadIdx.x;
    const int u   = tid >> 7;
    const int t   = tid & 127;
    const int bh  = bh_base + u;
    const int b   = bh >> 4;
    const int n   = bh & 15;
    const int g   = t >> 4;
    const int qc  = t & 15;

    const float4* amg = reinterpret_cast<const float4*>(AM + (size_t)bh * 4096);
    float4 row[8];
    #pragma unroll
    for (int i = 0; i < 8; i++) row[i] = __ldcs(&amg[t + 128 * i]);

    if (t < 64) {
        const float* base = g_qkv + (size_t)b * NQKV + n * DHEAD + t;
        qs[u][t]  = base[0];
        ks2[u][t] = base[1024];
        vs[u][t]  = base[2048];
    }
    __syncthreads();

    if (t < 32) {
        float s = qs[u][t] * qs[u][t] + qs[u][t + 32] * qs[u][t + 32];
        #pragma unroll
        for (int o = 16; o; o >>= 1) s += __shfl_xor_sync(0xffffffffu, s, o);
        if (t == 0) scq[u] = 1.0f / fmaxf(sqrtf(s), 1e-12f);
    } else if (t < 64) {
        int l = t - 32;
        float s = ks2[u][l] * ks2[u][l] + ks2[u][l + 32] * ks2[u][l + 32];
        #pragma unroll
        for (int o = 16; o; o >>= 1) s += __shfl_xor_sync(0xffffffffu, s, o);
        if (l == 0) sck[u] = 1.0f / fmaxf(sqrtf(s), 1e-12f);
    }
    __syncthreads();
    if (t < 64) { qs[u][t] *= scq[u]; ks2[u][t] *= sck[u]; }
    __syncthreads();
    if (t < 32) {
        float s = ks2[u][t] * qs[u][t] + ks2[u][t + 32] * qs[u][t + 32];
        #pragma unroll
        for (int o = 16; o; o >>= 1) s += __shfl_xor_sync(0xffffffffu, s, o);
        if (t == 0) kqd[u] = s;
    }
    __syncthreads();

    const float k0 = ks2[u][qc * 4 + 0], k1 = ks2[u][qc * 4 + 1],
                k2 = ks2[u][qc * 4 + 2], k3 = ks2[u][qc * 4 + 3];
    const float q0 = qs[u][qc * 4 + 0], q1 = qs[u][qc * 4 + 1],
                q2 = qs[u][qc * 4 + 2], q3 = qs[u][qc * 4 + 3];

    float dk[8], dq[8];
    #pragma unroll
    for (int i = 0; i < 8; i++) {
        dk[i] = fmaf(row[i].x, k0, fmaf(row[i].y, k1, fmaf(row[i].z, k2, row[i].w * k3)));
        dq[i] = fmaf(row[i].x, q0, fmaf(row[i].y, q1, fmaf(row[i].z, q2, row[i].w * q3)));
    }
    #pragma unroll
    for (int o = 8; o; o >>= 1) {
        #pragma unroll
        for (int i = 0; i < 8; i++) {
            dk[i] += __shfl_xor_sync(0xffffffffu, dk[i], o);
            dq[i] += __shfl_xor_sync(0xffffffffu, dq[i], o);
        }
    }
    if (qc == 0) {
        #pragma unroll
        for (int i = 0; i < 8; i++) {
            dks[u][g + 8 * i] = dk[i];
            dqs[u][g + 8 * i] = dq[i];
        }
    }
    __syncthreads();

    const float w = g_wr[(size_t)b * 32 + n];
    const float r = g_wr[(size_t)b * 32 + 16 + n];

    if (t < 64) {
        float vpv = w * (vs[u][t] - dks[u][t]);
        vps[u][t] = vpv;
        hout[(size_t)b * 1024 + n * DHEAD + t] = (dqs[u][t] + vpv * kqd[u]) * r;
    }
    __syncthreads();

    float4* og = reinterpret_cast<float4*>(AMout + (size_t)bh * 4096);
    #pragma unroll
    for (int i = 0; i < 8; i++) {
        const float vpv = vps[u][g + 8 * i];
        float4 o;
        o.x = fmaf(k0, vpv, row[i].x);
        o.y = fmaf(k1, vpv, row[i].y);
        o.z = fmaf(k2, vpv, row[i].z);
        o.w = fmaf(k3, vpv, row[i].w);
        __stcs(&og[t + 128 * i], o);
    }
}

// ---------------------------------------------------------------------------
// kernels
// ---------------------------------------------------------------------------
__global__ __launch_bounds__(256, 2) void gemm_half(
    const float* __restrict__ bias,
    const float* __restrict__ wb, const float* __restrict__ rb)
{
    extern __shared__ char smem[];
    gemm_body(smem_u32(smem), blockIdx.y * TM, blockIdx.x * TN, bias, wb, rb);
}

__global__ __launch_bounds__(256, 2) void mix_kernel(
    const float* __restrict__ bias,
    const float* __restrict__ wb, const float* __restrict__ rb,
    const float* __restrict__ AM,
    float* __restrict__ hout, float* __restrict__ AMout)
{
    extern __shared__ char smem[];
    const int bid = blockIdx.x;
    if (bid < GEMM_MIX_CTAS) {
        // gemm for m-blocks 4..7
        gemm_body(smem_u32(smem), (4 + bid / 33) * TM, (bid % 33) * TN, bias, wb, rb);
    } else {
        // am units for b < 512 (bh in [0, 8192))
        am_body((bid - GEMM_MIX_CTAS) * 2, AM, hout, AMout);
    }
}

__global__ __launch_bounds__(256) void am_half(
    const float* __restrict__ AM, float* __restrict__ hout, float* __restrict__ AMout)
{
    am_body((4096 + blockIdx.x) * 2, AM, hout, AMout);   // bh in [8192, 16384)
}

// ---------------------------------------------------------------------------
extern "C" void kernel_launch(void* const* d_in, const int* in_sizes, int n_in,
                              void* d_out, int out_size)
{
    const float* x      = (const float*)d_in[0];
    const float* h      = (const float*)d_in[1];
    const float* AM     = (const float*)d_in[2];
    const float* Wqkv_w = (const float*)d_in[3];
    const float* Wqkv_b = (const float*)d_in[4];
    const float* Ww_w   = (const float*)d_in[5];
    const float* Ww_b   = (const float*)d_in[6];
    const float* Wr_w   = (const float*)d_in[7];
    const float* Wr_b   = (const float*)d_in[8];

    float* out    = (float*)d_out;
    float* h_new  = out;
    float* AM_new = out + (size_t)B_ * 1024;

    cudaFuncSetAttribute(gemm_half,
                         cudaFuncAttributeMaxDynamicSharedMemorySize, SMEM_TOTAL);
    cudaFuncSetAttribute(mix_kernel,
                         cudaFuncAttributeMaxDynamicSharedMemorySize, SMEM_TOTAL);

    conv_all<<<4352, 256>>>(x, h, Wqkv_w, Ww_w, Wr_w);
    gemm_half<<<dim3(33, 4), 256, SMEM_TOTAL>>>(Wqkv_b, Ww_b, Wr_b);
    mix_kernel<<<GEMM_MIX_CTAS + 4096, 256, SMEM_TOTAL>>>(
        Wqkv_b, Ww_b, Wr_b, AM, h_new, AM_new);
    am_half<<<4096, 256>>>(AM, h_new, AM_new);
}

// round 16
// speedup vs baseline: 1.0704x; 1.0704x over previous
#include <cuda_runtime.h>
#include <cuda_bf16.h>
#include <cuda_fp16.h>
#include <math.h>
#include <cstdint>

// ---------------------------------------------------------------------------
// LSAMCell — Round 16 (converged best configuration).
//   conv_all : pure streaming fp32->fp16 (k-major W, no transpose)   ~9.5us
//   gemm     : fp16 mma.sync K=2048, CTA 128x96, trans-B, w/r fused  ~52us (90% HMMA peak)
//   am_update: warp-contiguous float4 streaming, 2 units/CTA         ~72us (93% HBM floor)
// ---------------------------------------------------------------------------

#define B_      1024
#define NQKV    3072
#define NPADW   3168               // g_W row width (33 tiles of 96)
#define KW      2048
#define NHEAD_  16
#define DHEAD   64

#define TM      128
#define TN      96
#define BK      64
#define STAGES  3
#define NST     32                 // 2048 / 64
#define PITCH   144                // A tile pitch (128B data + 16B skew)
#define PITCHB  208                // B tile pitch (192B data + 16B skew)
#define TILE_A  (TM * PITCH)       // 18432
#define TILE_Bz (BK * PITCHB)      // 13312
#define STAGE_BYTES (TILE_A + TILE_Bz)       // 31744
#define SMEM_TOTAL  (STAGES * STAGE_BYTES)   // 95232

__device__ float g_qkv[B_ * NQKV];
__device__ float g_wr [B_ * 32];
__device__ __align__(16) __half g_A[B_ * KW];      // fp16(xh), m-major
__device__ __align__(16) __half g_W[KW * NPADW];   // fp16(W), K-MAJOR; cols 3104.. zero

// ---------------------------------------------------------------------------
__device__ __forceinline__ uint32_t smem_u32(const void* p) {
    uint32_t a;
    asm("{ .reg .u64 t; cvta.to.shared.u64 t, %1; cvt.u32.u64 %0, t; }" : "=r"(a) : "l"(p));
    return a;
}
__device__ __forceinline__ void cp16(uint32_t dst, const void* src) {
    asm volatile("cp.async.cg.shared.global [%0], [%1], 16;" :: "r"(dst), "l"(src));
}
#define CP_COMMIT() asm volatile("cp.async.commit_group;" ::: "memory")
#define CP_WAIT(n)  asm volatile("cp.async.wait_group %0;" :: "n"(n) : "memory")

__device__ __forceinline__ void ldsm_x4(uint32_t (&r)[4], uint32_t addr) {
    asm volatile("ldmatrix.sync.aligned.m8n8.x4.shared.b16 {%0,%1,%2,%3}, [%4];"
                 : "=r"(r[0]), "=r"(r[1]), "=r"(r[2]), "=r"(r[3]) : "r"(addr));
}
__device__ __forceinline__ void ldsm_x4_t(uint32_t (&r)[4], uint32_t addr) {
    asm volatile("ldmatrix.sync.aligned.m8n8.x4.trans.shared.b16 {%0,%1,%2,%3}, [%4];"
                 : "=r"(r[0]), "=r"(r[1]), "=r"(r[2]), "=r"(r[3]) : "r"(addr));
}
__device__ __forceinline__ void mma16816(
    float (&c)[4], const uint32_t (&a)[4], uint32_t b0, uint32_t b1) {
    asm volatile(
        "mma.sync.aligned.m16n8k16.row.col.f32.f16.f16.f32 "
        "{%0,%1,%2,%3}, {%4,%5,%6,%7}, {%8,%9}, {%0,%1,%2,%3};"
        : "+f"(c[0]), "+f"(c[1]), "+f"(c[2]), "+f"(c[3])
        : "r"(a[0]), "r"(a[1]), "r"(a[2]), "r"(a[3]), "r"(b0), "r"(b1));
}

// ---------------------------------------------------------------------------
// merged conversion kernel (pure streaming, no smem)
// ---------------------------------------------------------------------------
__global__ __launch_bounds__(256) void conv_all(
    const float* __restrict__ X, const float* __restrict__ H,
    const float* __restrict__ W,
    const float* __restrict__ Ww, const float* __restrict__ Wr)
{
    const int bid = blockIdx.x;
    const int t   = threadIdx.x;

    if (bid < 1024) {
        #pragma unroll
        for (int it = 0; it < 2; it++) {
            int f = bid * 512 + t + it * 256;
            int m = f >> 9;
            int k = (f & 511) * 4;
            const float* src = (k < 1024) ? (X + (size_t)m * 1024 + k)
                                          : (H + (size_t)m * 1024 + (k - 1024));
            float4 v = *reinterpret_cast<const float4*>(src);
            __half hi[4];
            hi[0] = __float2half_rn(v.x);
            hi[1] = __float2half_rn(v.y);
            hi[2] = __float2half_rn(v.z);
            hi[3] = __float2half_rn(v.w);
            *reinterpret_cast<uint2*>(&g_A[(size_t)m * KW + k]) = *reinterpret_cast<uint2*>(hi);
        }
    } else if (bid < 4096) {
        #pragma unroll
        for (int it = 0; it < 2; it++) {
            int f = (bid - 1024) * 512 + t + it * 256;
            int k  = f / 768;
            int n4 = (f - k * 768) * 4;
            float4 v = *reinterpret_cast<const float4*>(&W[(size_t)k * NQKV + n4]);
            __half hi[4];
            hi[0] = __float2half_rn(v.x);
            hi[1] = __float2half_rn(v.y);
            hi[2] = __float2half_rn(v.z);
            hi[3] = __float2half_rn(v.w);
            *reinterpret_cast<uint2*>(&g_W[(size_t)k * NPADW + n4]) =
                *reinterpret_cast<uint2*>(hi);
        }
    } else {
        int idx = (bid - 4096) * 256 + t;
        int k = idx >> 5;
        int c = idx & 31;
        float v = (c < 16) ? Ww[(size_t)k * 16 + c] : Wr[(size_t)k * 16 + (c - 16)];
        g_W[(size_t)k * NPADW + NQKV + c] = __float2half_rn(v);
    }
}

// ---------------------------------------------------------------------------
// GEMM: [g_qkv | w/r] = fp16(xh) @ W (+bias / sigmoid), K=2048
// ---------------------------------------------------------------------------
__device__ __forceinline__ void load_stage(uint32_t sb, int t, int bm, int bn)
{
    const int tid = threadIdx.x;
    const uint32_t base = sb + (t % STAGES) * STAGE_BYTES;
    const __half* gA = g_A + t * BK;
    const __half* gB = g_W + (size_t)(t * BK) * NPADW + bn;
    #pragma unroll
    for (int i = 0; i < 4; i++) {
        int c = tid + i * 256;
        int row = c >> 3, cc = c & 7;
        cp16(base + row * PITCH + cc * 16, gA + (size_t)(bm + row) * KW + cc * 8);
    }
    #pragma unroll
    for (int i = 0; i < 3; i++) {
        int c = tid + i * 256;
        int row = c / 12, cc = c - row * 12;
        cp16(base + TILE_A + row * PITCHB + cc * 16,
             gB + (size_t)row * NPADW + cc * 8);
    }
    CP_COMMIT();
}

__global__ __launch_bounds__(256, 2) void gemm_qkv_mma(
    const float* __restrict__ bias,
    const float* __restrict__ wb, const float* __restrict__ rb)
{
    extern __shared__ char smem[];
    const uint32_t sb = smem_u32(smem);
    const int tid  = threadIdx.x;
    const int lane = tid & 31, wid = tid >> 5;
    const int wm = (wid & 3) * 32;
    const int wn = (wid >> 2) * 48;
    const int bn = blockIdx.x * TN;
    const int bm = blockIdx.y * TM;

    const int grp = lane >> 3;
    const int l7  = lane & 7;
    const int arow = wm + (grp & 1) * 8 + l7;
    const int achk = grp >> 1;
    const int bkrow = (grp & 1) * 8 + l7;
    const int bncol = wn + (grp >> 1) * 8;

    float acc[2][6][4];
    #pragma unroll
    for (int i = 0; i < 2; i++)
        #pragma unroll
        for (int j = 0; j < 6; j++)
            #pragma unroll
            for (int l = 0; l < 4; l++) acc[i][j][l] = 0.0f;

    load_stage(sb, 0, bm, bn);
    load_stage(sb, 1, bm, bn);

    for (int s = 0; s < NST; s++) {
        if (s + 2 < NST) { load_stage(sb, s + 2, bm, bn); CP_WAIT(2); }
        else if (s + 1 < NST) { CP_WAIT(1); }
        else { CP_WAIT(0); }
        __syncthreads();

        const uint32_t abase = sb + (s % STAGES) * STAGE_BYTES;
        const uint32_t bbase = abase + TILE_A;

        #pragma unroll
        for (int ks = 0; ks < 4; ks++) {
            uint32_t a[2][4], b[3][4];
            #pragma unroll
            for (int mf = 0; mf < 2; mf++)
                ldsm_x4(a[mf], abase + (arow + mf * 16) * PITCH + (achk + 2 * ks) * 16);
            #pragma unroll
            for (int nf = 0; nf < 3; nf++)
                ldsm_x4_t(b[nf], bbase + (ks * 16 + bkrow) * PITCHB
                                       + (bncol + nf * 16) * 2);
            #pragma unroll
            for (int mf = 0; mf < 2; mf++)
                #pragma unroll
                for (int nf = 0; nf < 3; nf++) {
                    mma16816(acc[mf][nf * 2 + 0], a[mf], b[nf][0], b[nf][1]);
                    mma16816(acc[mf][nf * 2 + 1], a[mf], b[nf][2], b[nf][3]);
                }
        }
        __syncthreads();
    }

    const int q = lane >> 2;
    const int n2 = (lane & 3) * 2;

    if (bn < NQKV) {
        #pragma unroll
        for (int ng = 0; ng < 6; ng++) {
            const int gn = bn + wn + ng * 8 + n2;
            const float bx = bias[gn], by = bias[gn + 1];
            #pragma unroll
            for (int mf = 0; mf < 2; mf++) {
                const int gm = bm + wm + mf * 16 + q;
                float2 lo = { acc[mf][ng][0] + bx, acc[mf][ng][1] + by };
                float2 hi = { acc[mf][ng][2] + bx, acc[mf][ng][3] + by };
                *reinterpret_cast<float2*>(&g_qkv[(size_t)gm * NQKV + gn])       = lo;
                *reinterpret_cast<float2*>(&g_qkv[(size_t)(gm + 8) * NQKV + gn]) = hi;
            }
        }
    } else {
        if (wn == 0) {
            #pragma unroll
            for (int ng = 0; ng < 4; ng++) {
                const int c0 = ng * 8 + n2;
                const float b0 = (c0 < 16) ? wb[c0] : rb[c0 - 16];
                const float b1 = (c0 + 1 < 16) ? wb[c0 + 1] : rb[c0 + 1 - 16];
                #pragma unroll
                for (int mf = 0; mf < 2; mf++) {
                    const int gm = bm + wm + mf * 16 + q;
                    g_wr[(size_t)gm * 32 + c0]     = 1.0f / (1.0f + expf(-(acc[mf][ng][0] + b0)));
                    g_wr[(size_t)gm * 32 + c0 + 1] = 1.0f / (1.0f + expf(-(acc[mf][ng][1] + b1)));
                    g_wr[(size_t)(gm + 8) * 32 + c0]     = 1.0f / (1.0f + expf(-(acc[mf][ng][2] + b0)));
                    g_wr[(size_t)(gm + 8) * 32 + c0 + 1] = 1.0f / (1.0f + expf(-(acc[mf][ng][3] + b1)));
                }
            }
        }
    }
}

// ---------------------------------------------------------------------------
// am_update (R12 measured-best): 2 units per 256-thread CTA,
// warp-contiguous float4 streaming.
// ---------------------------------------------------------------------------
__global__ __launch_bounds__(256) void am_update(
    const float* __restrict__ AM, float* __restrict__ hout, float* __restrict__ AMout)
{
    __shared__ float qs[2][64], ks2[2][64], vs[2][64];
    __shared__ float dks[2][64], dqs[2][64], vps[2][64];
    __shared__ float scq[2], sck[2], kqd[2];

    const int tid = threadIdx.x;
    const int u   = tid >> 7;
    const int t   = tid & 127;
    const int bh  = blockIdx.x * 2 + u;
    const int b   = bh >> 4;
    const int n   = bh & 15;
    const int g   = t >> 4;
    const int qc  = t & 15;

    const float4* amg = reinterpret_cast<const float4*>(AM + (size_t)bh * 4096);
    float4 row[8];
    #pragma unroll
    for (int i = 0; i < 8; i++) row[i] = __ldcs(&amg[t + 128 * i]);

    if (t < 64) {
        const float* base = g_qkv + (size_t)b * NQKV + n * DHEAD + t;
        qs[u][t]  = base[0];
        ks2[u][t] = base[1024];
        vs[u][t]  = base[2048];
    }
    __syncthreads();

    if (t < 32) {
        float s = qs[u][t] * qs[u][t] + qs[u][t + 32] * qs[u][t + 32];
        #pragma unroll
        for (int o = 16; o; o >>= 1) s += __shfl_xor_sync(0xffffffffu, s, o);
        if (t == 0) scq[u] = 1.0f / fmaxf(sqrtf(s), 1e-12f);
    } else if (t < 64) {
        int l = t - 32;
        float s = ks2[u][l] * ks2[u][l] + ks2[u][l + 32] * ks2[u][l + 32];
        #pragma unroll
        for (int o = 16; o; o >>= 1) s += __shfl_xor_sync(0xffffffffu, s, o);
        if (l == 0) sck[u] = 1.0f / fmaxf(sqrtf(s), 1e-12f);
    }
    __syncthreads();
    if (t < 64) { qs[u][t] *= scq[u]; ks2[u][t] *= sck[u]; }
    __syncthreads();
    if (t < 32) {
        float s = ks2[u][t] * qs[u][t] + ks2[u][t + 32] * qs[u][t + 32];
        #pragma unroll
        for (int o = 16; o; o >>= 1) s += __shfl_xor_sync(0xffffffffu, s, o);
        if (t == 0) kqd[u] = s;
    }
    __syncthreads();

    const float k0 = ks2[u][qc * 4 + 0], k1 = ks2[u][qc * 4 + 1],
                k2 = ks2[u][qc * 4 + 2], k3 = ks2[u][qc * 4 + 3];
    const float q0 = qs[u][qc * 4 + 0], q1 = qs[u][qc * 4 + 1],
                q2 = qs[u][qc * 4 + 2], q3 = qs[u][qc * 4 + 3];

    float dk[8], dq[8];
    #pragma unroll
    for (int i = 0; i < 8; i++) {
        dk[i] = fmaf(row[i].x, k0, fmaf(row[i].y, k1, fmaf(row[i].z, k2, row[i].w * k3)));
        dq[i] = fmaf(row[i].x, q0, fmaf(row[i].y, q1, fmaf(row[i].z, q2, row[i].w * q3)));
    }
    #pragma unroll
    for (int o = 8; o; o >>= 1) {
        #pragma unroll
        for (int i = 0; i < 8; i++) {
            dk[i] += __shfl_xor_sync(0xffffffffu, dk[i], o);
            dq[i] += __shfl_xor_sync(0xffffffffu, dq[i], o);
        }
    }
    if (qc == 0) {
        #pragma unroll
        for (int i = 0; i < 8; i++) {
            dks[u][g + 8 * i] = dk[i];
            dqs[u][g + 8 * i] = dq[i];
        }
    }
    __syncthreads();

    const float w = g_wr[(size_t)b * 32 + n];
    const float r = g_wr[(size_t)b * 32 + 16 + n];

    if (t < 64) {
        float vpv = w * (vs[u][t] - dks[u][t]);
        vps[u][t] = vpv;
        hout[(size_t)b * 1024 + n * DHEAD + t] = (dqs[u][t] + vpv * kqd[u]) * r;
    }
    __syncthreads();

    float4* og = reinterpret_cast<float4*>(AMout + (size_t)bh * 4096);
    #pragma unroll
    for (int i = 0; i < 8; i++) {
        const float vpv = vps[u][g + 8 * i];
        float4 o;
        o.x = fmaf(k0, vpv, row[i].x);
        o.y = fmaf(k1, vpv, row[i].y);
        o.z = fmaf(k2, vpv, row[i].z);
        o.w = fmaf(k3, vpv, row[i].w);
        __stcs(&og[t + 128 * i], o);
    }
}

// ---------------------------------------------------------------------------
extern "C" void kernel_launch(void* const* d_in, const int* in_sizes, int n_in,
                              void* d_out, int out_size)
{
    const float* x      = (const float*)d_in[0];
    const float* h      = (const float*)d_in[1];
    const float* AM     = (const float*)d_in[2];
    const float* Wqkv_w = (const float*)d_in[3];
    const float* Wqkv_b = (const float*)d_in[4];
    const float* Ww_w   = (const float*)d_in[5];
    const float* Ww_b   = (const float*)d_in[6];
    const float* Wr_w   = (const float*)d_in[7];
    const float* Wr_b   = (const float*)d_in[8];

    float* out    = (float*)d_out;
    float* h_new  = out;
    float* AM_new = out + (size_t)B_ * 1024;

    cudaFuncSetAttribute(gemm_qkv_mma,
                         cudaFuncAttributeMaxDynamicSharedMemorySize, SMEM_TOTAL);

    conv_all<<<4352, 256>>>(x, h, Wqkv_w, Ww_w, Wr_w);
    gemm_qkv_mma<<<dim3(NPADW / TN, B_ / TM), 256, SMEM_TOTAL>>>(Wqkv_b, Ww_b, Wr_b);
    am_update<<<B_ * NHEAD_ / 2, 256>>>(AM, h_new, AM_new);
}

// round 17
// speedup vs baseline: 1.0762x; 1.0055x over previous
#include <cuda_runtime.h>
#include <cuda_bf16.h>
#include <cuda_fp16.h>
#include <math.h>
#include <cstdint>

// ---------------------------------------------------------------------------
// LSAMCell — Round 17.
//   R16 converged config + single-__syncthreads GEMM mainloop
//   (wait -> sync -> issue load(s+2) -> compute(s); safe with 3 buffers).
//   conv_all : pure streaming fp32->fp16 (k-major W)                 ~9.2us
//   gemm     : fp16 mma.sync K=2048, CTA 128x96, trans-B, w/r fused
//   am_update: warp-contiguous float4 streaming, 2 units/CTA         ~72us
// ---------------------------------------------------------------------------

#define B_      1024
#define NQKV    3072
#define NPADW   3168               // g_W row width (33 tiles of 96)
#define KW      2048
#define NHEAD_  16
#define DHEAD   64

#define TM      128
#define TN      96
#define BK      64
#define STAGES  3
#define NST     32                 // 2048 / 64
#define PITCH   144                // A tile pitch (128B data + 16B skew)
#define PITCHB  208                // B tile pitch (192B data + 16B skew)
#define TILE_A  (TM * PITCH)       // 18432
#define TILE_Bz (BK * PITCHB)      // 13312
#define STAGE_BYTES (TILE_A + TILE_Bz)       // 31744
#define SMEM_TOTAL  (STAGES * STAGE_BYTES)   // 95232

__device__ float g_qkv[B_ * NQKV];
__device__ float g_wr [B_ * 32];
__device__ __align__(16) __half g_A[B_ * KW];      // fp16(xh), m-major
__device__ __align__(16) __half g_W[KW * NPADW];   // fp16(W), K-MAJOR; cols 3104.. zero

// ---------------------------------------------------------------------------
__device__ __forceinline__ uint32_t smem_u32(const void* p) {
    uint32_t a;
    asm("{ .reg .u64 t; cvta.to.shared.u64 t, %1; cvt.u32.u64 %0, t; }" : "=r"(a) : "l"(p));
    return a;
}
__device__ __forceinline__ void cp16(uint32_t dst, const void* src) {
    asm volatile("cp.async.cg.shared.global [%0], [%1], 16;" :: "r"(dst), "l"(src));
}
#define CP_COMMIT() asm volatile("cp.async.commit_group;" ::: "memory")
#define CP_WAIT(n)  asm volatile("cp.async.wait_group %0;" :: "n"(n) : "memory")

__device__ __forceinline__ void ldsm_x4(uint32_t (&r)[4], uint32_t addr) {
    asm volatile("ldmatrix.sync.aligned.m8n8.x4.shared.b16 {%0,%1,%2,%3}, [%4];"
                 : "=r"(r[0]), "=r"(r[1]), "=r"(r[2]), "=r"(r[3]) : "r"(addr));
}
__device__ __forceinline__ void ldsm_x4_t(uint32_t (&r)[4], uint32_t addr) {
    asm volatile("ldmatrix.sync.aligned.m8n8.x4.trans.shared.b16 {%0,%1,%2,%3}, [%4];"
                 : "=r"(r[0]), "=r"(r[1]), "=r"(r[2]), "=r"(r[3]) : "r"(addr));
}
__device__ __forceinline__ void mma16816(
    float (&c)[4], const uint32_t (&a)[4], uint32_t b0, uint32_t b1) {
    asm volatile(
        "mma.sync.aligned.m16n8k16.row.col.f32.f16.f16.f32 "
        "{%0,%1,%2,%3}, {%4,%5,%6,%7}, {%8,%9}, {%0,%1,%2,%3};"
        : "+f"(c[0]), "+f"(c[1]), "+f"(c[2]), "+f"(c[3])
        : "r"(a[0]), "r"(a[1]), "r"(a[2]), "r"(a[3]), "r"(b0), "r"(b1));
}

// ---------------------------------------------------------------------------
// merged conversion kernel (pure streaming, no smem)
// ---------------------------------------------------------------------------
__global__ __launch_bounds__(256) void conv_all(
    const float* __restrict__ X, const float* __restrict__ H,
    const float* __restrict__ W,
    const float* __restrict__ Ww, const float* __restrict__ Wr)
{
    const int bid = blockIdx.x;
    const int t   = threadIdx.x;

    if (bid < 1024) {
        #pragma unroll
        for (int it = 0; it < 2; it++) {
            int f = bid * 512 + t + it * 256;
            int m = f >> 9;
            int k = (f & 511) * 4;
            const float* src = (k < 1024) ? (X + (size_t)m * 1024 + k)
                                          : (H + (size_t)m * 1024 + (k - 1024));
            float4 v = *reinterpret_cast<const float4*>(src);
            __half hi[4];
            hi[0] = __float2half_rn(v.x);
            hi[1] = __float2half_rn(v.y);
            hi[2] = __float2half_rn(v.z);
            hi[3] = __float2half_rn(v.w);
            *reinterpret_cast<uint2*>(&g_A[(size_t)m * KW + k]) = *reinterpret_cast<uint2*>(hi);
        }
    } else if (bid < 4096) {
        #pragma unroll
        for (int it = 0; it < 2; it++) {
            int f = (bid - 1024) * 512 + t + it * 256;
            int k  = f / 768;
            int n4 = (f - k * 768) * 4;
            float4 v = *reinterpret_cast<const float4*>(&W[(size_t)k * NQKV + n4]);
            __half hi[4];
            hi[0] = __float2half_rn(v.x);
            hi[1] = __float2half_rn(v.y);
            hi[2] = __float2half_rn(v.z);
            hi[3] = __float2half_rn(v.w);
            *reinterpret_cast<uint2*>(&g_W[(size_t)k * NPADW + n4]) =
                *reinterpret_cast<uint2*>(hi);
        }
    } else {
        int idx = (bid - 4096) * 256 + t;
        int k = idx >> 5;
        int c = idx & 31;
        float v = (c < 16) ? Ww[(size_t)k * 16 + c] : Wr[(size_t)k * 16 + (c - 16)];
        g_W[(size_t)k * NPADW + NQKV + c] = __float2half_rn(v);
    }
}

// ---------------------------------------------------------------------------
// GEMM: [g_qkv | w/r] = fp16(xh) @ W (+bias / sigmoid), K=2048
// Single-sync mainloop: wait -> sync -> issue(s+2) -> compute(s).
// ---------------------------------------------------------------------------
__device__ __forceinline__ void load_stage(uint32_t sb, int t, int bm, int bn)
{
    const int tid = threadIdx.x;
    const uint32_t base = sb + (t % STAGES) * STAGE_BYTES;
    const __half* gA = g_A + t * BK;
    const __half* gB = g_W + (size_t)(t * BK) * NPADW + bn;
    #pragma unroll
    for (int i = 0; i < 4; i++) {
        int c = tid + i * 256;
        int row = c >> 3, cc = c & 7;
        cp16(base + row * PITCH + cc * 16, gA + (size_t)(bm + row) * KW + cc * 8);
    }
    #pragma unroll
    for (int i = 0; i < 3; i++) {
        int c = tid + i * 256;
        int row = c / 12, cc = c - row * 12;
        cp16(base + TILE_A + row * PITCHB + cc * 16,
             gB + (size_t)row * NPADW + cc * 8);
    }
    CP_COMMIT();
}

__global__ __launch_bounds__(256, 2) void gemm_qkv_mma(
    const float* __restrict__ bias,
    const float* __restrict__ wb, const float* __restrict__ rb)
{
    extern __shared__ char smem[];
    const uint32_t sb = smem_u32(smem);
    const int tid  = threadIdx.x;
    const int lane = tid & 31, wid = tid >> 5;
    const int wm = (wid & 3) * 32;
    const int wn = (wid >> 2) * 48;
    const int bn = blockIdx.x * TN;
    const int bm = blockIdx.y * TM;

    const int grp = lane >> 3;
    const int l7  = lane & 7;
    const int arow = wm + (grp & 1) * 8 + l7;
    const int achk = grp >> 1;
    const int bkrow = (grp & 1) * 8 + l7;
    const int bncol = wn + (grp >> 1) * 8;

    float acc[2][6][4];
    #pragma unroll
    for (int i = 0; i < 2; i++)
        #pragma unroll
        for (int j = 0; j < 6; j++)
            #pragma unroll
            for (int l = 0; l < 4; l++) acc[i][j][l] = 0.0f;

    load_stage(sb, 0, bm, bn);
    load_stage(sb, 1, bm, bn);

    for (int s = 0; s < NST; s++) {
        if (s == NST - 1) { CP_WAIT(0); } else { CP_WAIT(1); }
        __syncthreads();                     // single barrier per stage
        if (s + 2 < NST) load_stage(sb, s + 2, bm, bn);

        const uint32_t abase = sb + (s % STAGES) * STAGE_BYTES;
        const uint32_t bbase = abase + TILE_A;

        #pragma unroll
        for (int ks = 0; ks < 4; ks++) {
            uint32_t a[2][4], b[3][4];
            #pragma unroll
            for (int mf = 0; mf < 2; mf++)
                ldsm_x4(a[mf], abase + (arow + mf * 16) * PITCH + (achk + 2 * ks) * 16);
            #pragma unroll
            for (int nf = 0; nf < 3; nf++)
                ldsm_x4_t(b[nf], bbase + (ks * 16 + bkrow) * PITCHB
                                       + (bncol + nf * 16) * 2);
            #pragma unroll
            for (int mf = 0; mf < 2; mf++)
                #pragma unroll
                for (int nf = 0; nf < 3; nf++) {
                    mma16816(acc[mf][nf * 2 + 0], a[mf], b[nf][0], b[nf][1]);
                    mma16816(acc[mf][nf * 2 + 1], a[mf], b[nf][2], b[nf][3]);
                }
        }
    }

    const int q = lane >> 2;
    const int n2 = (lane & 3) * 2;

    if (bn < NQKV) {
        #pragma unroll
        for (int ng = 0; ng < 6; ng++) {
            const int gn = bn + wn + ng * 8 + n2;
            const float bx = bias[gn], by = bias[gn + 1];
            #pragma unroll
            for (int mf = 0; mf < 2; mf++) {
                const int gm = bm + wm + mf * 16 + q;
                float2 lo = { acc[mf][ng][0] + bx, acc[mf][ng][1] + by };
                float2 hi = { acc[mf][ng][2] + bx, acc[mf][ng][3] + by };
                *reinterpret_cast<float2*>(&g_qkv[(size_t)gm * NQKV + gn])       = lo;
                *reinterpret_cast<float2*>(&g_qkv[(size_t)(gm + 8) * NQKV + gn]) = hi;
            }
        }
    } else {
        if (wn == 0) {
            #pragma unroll
            for (int ng = 0; ng < 4; ng++) {
                const int c0 = ng * 8 + n2;
                const float b0 = (c0 < 16) ? wb[c0] : rb[c0 - 16];
                const float b1 = (c0 + 1 < 16) ? wb[c0 + 1] : rb[c0 + 1 - 16];
                #pragma unroll
                for (int mf = 0; mf < 2; mf++) {
                    const int gm = bm + wm + mf * 16 + q;
                    g_wr[(size_t)gm * 32 + c0]     = 1.0f / (1.0f + expf(-(acc[mf][ng][0] + b0)));
                    g_wr[(size_t)gm * 32 + c0 + 1] = 1.0f / (1.0f + expf(-(acc[mf][ng][1] + b1)));
                    g_wr[(size_t)(gm + 8) * 32 + c0]     = 1.0f / (1.0f + expf(-(acc[mf][ng][2] + b0)));
                    g_wr[(size_t)(gm + 8) * 32 + c0 + 1] = 1.0f / (1.0f + expf(-(acc[mf][ng][3] + b1)));
                }
            }
        }
    }
}

// ---------------------------------------------------------------------------
// am_update (measured best): 2 units per 256-thread CTA,
// warp-contiguous float4 streaming.
// ---------------------------------------------------------------------------
__global__ __launch_bounds__(256) void am_update(
    const float* __restrict__ AM, float* __restrict__ hout, float* __restrict__ AMout)
{
    __shared__ float qs[2][64], ks2[2][64], vs[2][64];
    __shared__ float dks[2][64], dqs[2][64], vps[2][64];
    __shared__ float scq[2], sck[2], kqd[2];

    const int tid = threadIdx.x;
    const int u   = tid >> 7;
    const int t   = tid & 127;
    const int bh  = blockIdx.x * 2 + u;
    const int b   = bh >> 4;
    const int n   = bh & 15;
    const int g   = t >> 4;
    const int qc  = t & 15;

    const float4* amg = reinterpret_cast<const float4*>(AM + (size_t)bh * 4096);
    float4 row[8];
    #pragma unroll
    for (int i = 0; i < 8; i++) row[i] = __ldcs(&amg[t + 128 * i]);

    if (t < 64) {
        const float* base = g_qkv + (size_t)b * NQKV + n * DHEAD + t;
        qs[u][t]  = base[0];
        ks2[u][t] = base[1024];
        vs[u][t]  = base[2048];
    }
    __syncthreads();

    if (t < 32) {
        float s = qs[u][t] * qs[u][t] + qs[u][t + 32] * qs[u][t + 32];
        #pragma unroll
        for (int o = 16; o; o >>= 1) s += __shfl_xor_sync(0xffffffffu, s, o);
        if (t == 0) scq[u] = 1.0f / fmaxf(sqrtf(s), 1e-12f);
    } else if (t < 64) {
        int l = t - 32;
        float s = ks2[u][l] * ks2[u][l] + ks2[u][l + 32] * ks2[u][l + 32];
        #pragma unroll
        for (int o = 16; o; o >>= 1) s += __shfl_xor_sync(0xffffffffu, s, o);
        if (l == 0) sck[u] = 1.0f / fmaxf(sqrtf(s), 1e-12f);
    }
    __syncthreads();
    if (t < 64) { qs[u][t] *= scq[u]; ks2[u][t] *= sck[u]; }
    __syncthreads();
    if (t < 32) {
        float s = ks2[u][t] * qs[u][t] + ks2[u][t + 32] * qs[u][t + 32];
        #pragma unroll
        for (int o = 16; o; o >>= 1) s += __shfl_xor_sync(0xffffffffu, s, o);
        if (t == 0) kqd[u] = s;
    }
    __syncthreads();

    const float k0 = ks2[u][qc * 4 + 0], k1 = ks2[u][qc * 4 + 1],
                k2 = ks2[u][qc * 4 + 2], k3 = ks2[u][qc * 4 + 3];
    const float q0 = qs[u][qc * 4 + 0], q1 = qs[u][qc * 4 + 1],
                q2 = qs[u][qc * 4 + 2], q3 = qs[u][qc * 4 + 3];

    float dk[8], dq[8];
    #pragma unroll
    for (int i = 0; i < 8; i++) {
        dk[i] = fmaf(row[i].x, k0, fmaf(row[i].y, k1, fmaf(row[i].z, k2, row[i].w * k3)));
        dq[i] = fmaf(row[i].x, q0, fmaf(row[i].y, q1, fmaf(row[i].z, q2, row[i].w * q3)));
    }
    #pragma unroll
    for (int o = 8; o; o >>= 1) {
        #pragma unroll
        for (int i = 0; i < 8; i++) {
            dk[i] += __shfl_xor_sync(0xffffffffu, dk[i], o);
            dq[i] += __shfl_xor_sync(0xffffffffu, dq[i], o);
        }
    }
    if (qc == 0) {
        #pragma unroll
        for (int i = 0; i < 8; i++) {
            dks[u][g + 8 * i] = dk[i];
            dqs[u][g + 8 * i] = dq[i];
        }
    }
    __syncthreads();

    const float w = g_wr[(size_t)b * 32 + n];
    const float r = g_wr[(size_t)b * 32 + 16 + n];

    if (t < 64) {
        float vpv = w * (vs[u][t] - dks[u][t]);
        vps[u][t] = vpv;
        hout[(size_t)b * 1024 + n * DHEAD + t] = (dqs[u][t] + vpv * kqd[u]) * r;
    }
    __syncthreads();

    float4* og = reinterpret_cast<float4*>(AMout + (size_t)bh * 4096);
    #pragma unroll
    for (int i = 0; i < 8; i++) {
        const float vpv = vps[u][g + 8 * i];
        float4 o;
        o.x = fmaf(k0, vpv, row[i].x);
        o.y = fmaf(k1, vpv, row[i].y);
        o.z = fmaf(k2, vpv, row[i].z);
        o.w = fmaf(k3, vpv, row[i].w);
        __stcs(&og[t + 128 * i], o);
    }
}

// ---------------------------------------------------------------------------
extern "C" void kernel_launch(void* const* d_in, const int* in_sizes, int n_in,
                              void* d_out, int out_size)
{
    const float* x      = (const float*)d_in[0];
    const float* h      = (const float*)d_in[1];
    const float* AM     = (const float*)d_in[2];
    const float* Wqkv_w = (const float*)d_in[3];
    const float* Wqkv_b = (const float*)d_in[4];
    const float* Ww_w   = (const float*)d_in[5];
    const float* Ww_b   = (const float*)d_in[6];
    const float* Wr_w   = (const float*)d_in[7];
    const float* Wr_b   = (const float*)d_in[8];

    float* out    = (float*)d_out;
    float* h_new  = out;
    float* AM_new = out + (size_t)B_ * 1024;

    cudaFuncSetAttribute(gemm_qkv_mma,
                         cudaFuncAttributeMaxDynamicSharedMemorySize, SMEM_TOTAL);

    conv_all<<<4352, 256>>>(x, h, Wqkv_w, Ww_w, Wr_w);
    gemm_qkv_mma<<<dim3(NPADW / TN, B_ / TM), 256, SMEM_TOTAL>>>(Wqkv_b, Ww_b, Wr_b);
    am_update<<<B_ * NHEAD_ / 2, 256>>>(AM, h_new, AM_new);
}